// round 2
// baseline (speedup 1.0000x reference)
// R2: identical to R1 kernel — R1 was an infra failure (container died twice),
// no signal received. Re-audited for correctness; resubmitting unchanged.
#include <cuda_runtime.h>
#include <math.h>

#define BB 4
#define NN 2048
#define MM 4096
#define FARV 100000.0f

// ---------------- scratch (device globals; no allocation) ----------------
__device__ float4 g_pc4[BB*MM];          // contact points + norm
__device__ float  g_pos[BB*NN];          // success flag
__device__ float  g_pri[BB*NN];          // priority (r for negatives, +inf for positives)
__device__ float  g_wlab[BB*NN];         // gathered width label
__device__ float4 g_G4 [BB*NN*4];        // G,  padded to 16 floats per point
__device__ float4 g_Gs4[BB*NN*4];        // Gs, padded to 16 floats per point
__device__ float  g_gn [BB*NN];
__device__ float  g_gsn[BB*NN];
__device__ double g_acc[BB*8];           // per batch: 0 posSum, 1 bceSum, 2 selSum, 3 wlSum, 4 addsSum

__constant__ float c_lo[10] = {0.0f, 0.00794435329f, 0.0158887021f, 0.0238330509f, 0.0317773996f,
                               0.0397217484f, 0.0476660972f, 0.0556104459f, 0.0635547947f, 0.0714991435f};
__constant__ float c_hi[10] = {0.00794435329f, 0.0158887021f, 0.0238330509f, 0.0317773996f, 0.0397217484f,
                               0.0476660972f, 0.0556104459f, 0.0635547947f, 0.0714991435f, 0.08f};
__constant__ float c_wt[10] = {0.16652107f, 0.21488856f, 0.37031708f, 0.55618503f, 0.75124664f,
                               0.93943357f, 1.07824539f, 1.19423112f, 1.55731375f, 2.34173634f};

// ---------------- threefry2x32 (JAX-exact, key(42), counts = iota(8192)) ----------------
__device__ __forceinline__ unsigned rotl32(unsigned x, unsigned d){ return (x<<d)|(x>>(32u-d)); }

__device__ __forceinline__ float threefry_uniform_8192(unsigned flat){
  unsigned c0, c1; bool second;
  if (flat < 4096u){ c0 = flat;        c1 = flat + 4096u; second = false; }
  else             { c0 = flat - 4096u; c1 = flat;        second = true;  }
  const unsigned ks0 = 0u, ks1 = 42u, ks2 = 0u ^ 42u ^ 0x1BD11BDAu;
  unsigned x0 = c0 + ks0, x1 = c1 + ks1;
#define TF_ROUND(r) { x0 += x1; x1 = rotl32(x1,(r)); x1 ^= x0; }
  TF_ROUND(13) TF_ROUND(15) TF_ROUND(26) TF_ROUND(6)
  x0 += ks1; x1 += ks2 + 1u;
  TF_ROUND(17) TF_ROUND(29) TF_ROUND(16) TF_ROUND(24)
  x0 += ks2; x1 += ks0 + 2u;
  TF_ROUND(13) TF_ROUND(15) TF_ROUND(26) TF_ROUND(6)
  x0 += ks0; x1 += ks1 + 3u;
  TF_ROUND(17) TF_ROUND(29) TF_ROUND(16) TF_ROUND(24)
  x0 += ks1; x1 += ks2 + 4u;
  TF_ROUND(13) TF_ROUND(15) TF_ROUND(26) TF_ROUND(6)
  x0 += ks2; x1 += ks0 + 5u;
#undef TF_ROUND
  unsigned bits = second ? x1 : x0;
  float f = __uint_as_float((bits >> 9) | 0x3F800000u) - 1.0f;
  return fmaxf(f, 0.0f);
}

// ---------------- K0: prep contact float4 + zero accumulators ----------------
__global__ void k_prep(const float* __restrict__ pcp){
  int i = blockIdx.x*blockDim.x + threadIdx.x;
  if (i < BB*8) g_acc[i] = 0.0;
  if (i < BB*MM){
    float x = pcp[i*3+0], y = pcp[i*3+1], z = pcp[i*3+2];
    g_pc4[i] = make_float4(x, y, z, x*x + y*y + z*z);
  }
}

// ---------------- K1: nearest neighbor + threefry + G/Gs precompute ----------------
// warp handles 4 queries; block = 8 warps = 32 queries (batch-aligned)
__global__ __launch_bounds__(256) void k_nn(
    const float* __restrict__ pred_points,
    const float* __restrict__ pcw,
    const float* __restrict__ pcr,
    const float* __restrict__ pct,
    const float* __restrict__ cp,
    const float* __restrict__ cps)
{
  __shared__ float s_cp[15], s_cps[15];
  __shared__ float s_psum[8];
  int tid = threadIdx.x, lane = tid & 31, warp = tid >> 5;
  if (tid < 15){ s_cp[tid] = cp[tid]; s_cps[tid] = cps[tid]; }
  __syncthreads();

  int q0 = (blockIdx.x*8 + warp)*4;
  int b  = q0 / NN;

  float qx[4], qy[4], qz[4], qn[4];
#pragma unroll
  for (int k = 0; k < 4; k++){
    const float* p = pred_points + (size_t)(q0+k)*3;
    qx[k]=p[0]; qy[k]=p[1]; qz[k]=p[2];
    qn[k]=qx[k]*qx[k]+qy[k]*qy[k]+qz[k]*qz[k];
  }
  float best[4] = {3.4e38f,3.4e38f,3.4e38f,3.4e38f};
  int   bidx[4] = {0,0,0,0};
  const float4* pc = g_pc4 + (size_t)b*MM;
  for (int j = lane; j < MM; j += 32){
    float4 c = pc[j];
#pragma unroll
    for (int k = 0; k < 4; k++){
      float dot = qx[k]*c.x + qy[k]*c.y + qz[k]*c.z;
      float d = qn[k] + c.w - 2.0f*dot;
      d = fmaxf(d, 0.0f);
      if (d < best[k]){ best[k] = d; bidx[k] = j; }
    }
  }
#pragma unroll
  for (int k = 0; k < 4; k++){
#pragma unroll
    for (int off = 16; off; off >>= 1){
      float ov = __shfl_xor_sync(0xffffffffu, best[k], off);
      int   oi = __shfl_xor_sync(0xffffffffu, bidx[k], off);
      if (ov < best[k] || (ov == best[k] && oi < bidx[k])){ best[k]=ov; bidx[k]=oi; }
    }
  }

  float myPos = 0.0f;
  if (lane < 4){
    int k = lane;
    int q = q0 + k;
    int mi = bidx[k];
    float success = (best[k] < 2.5e-5f) ? 1.0f : 0.0f;  // RADIUS^2
    myPos = success;
    g_pos[q]  = success;
    g_wlab[q] = pcw[(size_t)b*MM + mi];
    float r = threefry_uniform_8192((unsigned)q);
    g_pri[q] = (success > 0.5f) ? __int_as_float(0x7f800000) : r;

    float Rm[9], Tv[3];
    if (success > 0.5f){
      const float* rp = pcr + ((size_t)b*MM + mi)*9;
#pragma unroll
      for (int u = 0; u < 9; u++) Rm[u] = rp[u];
      const float* tp = pct + ((size_t)b*MM + mi)*3;
      Tv[0]=tp[0]; Tv[1]=tp[1]; Tv[2]=tp[2];
    } else {
#pragma unroll
      for (int u = 0; u < 9; u++) Rm[u] = FARV;
      Tv[0]=FARV; Tv[1]=FARV; Tv[2]=FARV;
    }
    float* Gp  = (float*)(g_G4  + (size_t)q*4);
    float* Gsp = (float*)(g_Gs4 + (size_t)q*4);
    float gn = 0.0f, gsn = 0.0f;
#pragma unroll
    for (int c = 0; c < 5; c++){
#pragma unroll
      for (int d = 0; d < 3; d++){
        float v  = Rm[d*3+0]*s_cp [c*3+0] + Rm[d*3+1]*s_cp [c*3+1] + Rm[d*3+2]*s_cp [c*3+2] + Tv[d];
        float vs = Rm[d*3+0]*s_cps[c*3+0] + Rm[d*3+1]*s_cps[c*3+1] + Rm[d*3+2]*s_cps[c*3+2] + Tv[d];
        Gp [c*3+d] = v;  gn  += v*v;
        Gsp[c*3+d] = vs; gsn += vs*vs;
      }
    }
    Gp[15] = 0.0f; Gsp[15] = 0.0f;
    g_gn[q] = gn; g_gsn[q] = gsn;
  }

  // block reduce posSum (all warps in block are in same batch)
  float ps = myPos;
#pragma unroll
  for (int off = 16; off; off >>= 1) ps += __shfl_xor_sync(0xffffffffu, ps, off);
  if (lane == 0) s_psum[warp] = ps;
  __syncthreads();
  if (tid == 0){
    double t = 0.0;
    for (int w = 0; w < 8; w++) t += (double)s_psum[w];
    atomicAdd(&g_acc[b*8+0], t);
  }
}

// ---------------- K2: rank-based negative selection + bce + width loss ----------------
// warp per element; block = 8 warps (batch-aligned)
__global__ __launch_bounds__(256) void k_sel(
    const float* __restrict__ scores,
    const float* __restrict__ gwh)
{
  __shared__ float sb[8], ss[8], sw[8];
  int tid = threadIdx.x, lane = tid & 31, warp = tid >> 5;
  int i = blockIdx.x*8 + warp;
  int b = i / NN, n = i % NN;

  float mypri = g_pri[i];
  const float* pri = g_pri + (size_t)b*NN;
  int cnt = 0;
  for (int j = lane; j < NN; j += 32){
    float pj = pri[j];
    if (pj < mypri || (pj == mypri && j < n)) cnt++;
  }
#pragma unroll
  for (int off = 16; off; off >>= 1) cnt += __shfl_xor_sync(0xffffffffu, cnt, off);

  float bcesel = 0.0f, selv = 0.0f, wlc = 0.0f;
  if (lane == 0){
    float pos = g_pos[i];
    float neg = 1.0f - pos;
    double nPos = g_acc[b*8+0];
    float kk = (nPos > 0.0) ? (float)nPos : 2.0f;
    float sel_neg = (neg > 0.5f && (float)cnt < kk) ? 1.0f : 0.0f;
    float sel = pos + sel_neg;
    float p = scores[i];
    p = fminf(fmaxf(p, 1e-7f), 1.0f - 1e-7f);
    float bce = -(pos*logf(p) + (1.0f - pos)*logf(1.0f - p));
    bcesel = bce*sel; selv = sel;

    float w = g_wlab[i];
    float acc = 0.0f;
#pragma unroll
    for (int kb = 0; kb < 10; kb++){
      float mh = (w >= c_lo[kb] && w < c_hi[kb]) ? 1.0f : 0.0f;
      float x = gwh[(size_t)b*10*NN + (size_t)kb*NN + n];
      float bw = fmaxf(x, 0.0f) - x*mh + log1pf(expf(-fabsf(x)));
      acc += c_wt[kb]*bw;
    }
    wlc = (acc * 0.1f) * pos;
  }
  if (lane == 0){ sb[warp]=bcesel; ss[warp]=selv; sw[warp]=wlc; }
  __syncthreads();
  if (tid == 0){
    double a=0, c=0, d=0;
    for (int w = 0; w < 8; w++){ a += (double)sb[w]; c += (double)ss[w]; d += (double)sw[w]; }
    atomicAdd(&g_acc[b*8+1], a);
    atomicAdd(&g_acc[b*8+2], c);
    atomicAdd(&g_acc[b*8+3], d);
  }
}

// ---------------- K3: ADD-S min over control-point clouds ----------------
__device__ __forceinline__ float dot16(const float* P, float4 a0, float4 a1, float4 a2, float4 a3){
  return P[0]*a0.x + P[1]*a0.y + P[2]*a0.z + P[3]*a0.w
       + P[4]*a1.x + P[5]*a1.y + P[6]*a1.z + P[7]*a1.w
       + P[8]*a2.x + P[9]*a2.y + P[10]*a2.z + P[11]*a2.w
       + P[12]*a3.x + P[13]*a3.y + P[14]*a3.z + P[15]*a3.w;
}

// warp handles 2 queries; block = 8 warps = 16 queries; j tiled in smem (128/tile)
__global__ __launch_bounds__(256) void k_adds(
    const float* __restrict__ grasps,
    const float* __restrict__ scores,
    const float* __restrict__ cp)
{
  __shared__ float4 sG [128*4];
  __shared__ float4 sGs[128*4];
  __shared__ float2 sn [128];
  __shared__ float  s_cp[15];
  __shared__ float  s_part[8];

  int tid = threadIdx.x, lane = tid & 31, warp = tid >> 5;
  if (tid < 15) s_cp[tid] = cp[tid];
  __syncthreads();

  int iBase = blockIdx.x*16;
  int b  = iBase / NN;
  int i0 = iBase + warp*2;

  float P0[16], P1[16], pn0 = 0.0f, pn1 = 0.0f;
  {
    const float* gm = grasps + (size_t)i0*16;
#pragma unroll
    for (int c = 0; c < 5; c++)
#pragma unroll
      for (int d = 0; d < 3; d++){
        float v = gm[d*4+0]*s_cp[c*3+0] + gm[d*4+1]*s_cp[c*3+1] + gm[d*4+2]*s_cp[c*3+2] + gm[d*4+3];
        P0[c*3+d] = v; pn0 += v*v;
      }
    P0[15] = 0.0f;
    const float* gm1 = gm + 16;
#pragma unroll
    for (int c = 0; c < 5; c++)
#pragma unroll
      for (int d = 0; d < 3; d++){
        float v = gm1[d*4+0]*s_cp[c*3+0] + gm1[d*4+1]*s_cp[c*3+1] + gm1[d*4+2]*s_cp[c*3+2] + gm1[d*4+3];
        P1[c*3+d] = v; pn1 += v*v;
      }
    P1[15] = 0.0f;
  }

  float m0 = 3.4e38f, m1 = 3.4e38f;
  for (int t = 0; t < NN/128; t++){
    __syncthreads();
    int jb = t*128;
    const float4* Gp  = g_G4  + ((size_t)b*NN + jb)*4;
    const float4* Gsp = g_Gs4 + ((size_t)b*NN + jb)*4;
    for (int u = tid; u < 512; u += 256){ sG[u] = Gp[u]; sGs[u] = Gsp[u]; }
    if (tid < 128) sn[tid] = make_float2(g_gn[(size_t)b*NN + jb + tid], g_gsn[(size_t)b*NN + jb + tid]);
    __syncthreads();
#pragma unroll
    for (int u = 0; u < 4; u++){
      int jj = lane + u*32;
      float4 a0 = sG[jj*4+0], a1 = sG[jj*4+1], a2 = sG[jj*4+2], a3 = sG[jj*4+3];
      float2 nv = sn[jj];
      float d0 = dot16(P0, a0, a1, a2, a3);
      float d1 = dot16(P1, a0, a1, a2, a3);
      m0 = fminf(m0, pn0 + nv.x - 2.0f*d0);
      m1 = fminf(m1, pn1 + nv.x - 2.0f*d1);
      float4 c0 = sGs[jj*4+0], c1 = sGs[jj*4+1], c2 = sGs[jj*4+2], c3 = sGs[jj*4+3];
      float e0 = dot16(P0, c0, c1, c2, c3);
      float e1 = dot16(P1, c0, c1, c2, c3);
      m0 = fminf(m0, pn0 + nv.y - 2.0f*e0);
      m1 = fminf(m1, pn1 + nv.y - 2.0f*e1);
    }
  }
#pragma unroll
  for (int off = 16; off; off >>= 1){
    m0 = fminf(m0, __shfl_xor_sync(0xffffffffu, m0, off));
    m1 = fminf(m1, __shfl_xor_sync(0xffffffffu, m1, off));
  }
  float contrib = 0.0f;
  if (lane == 0){
    float v0 = g_pos[i0]   * sqrtf(fmaxf(m0, 0.0f) + 1e-12f) * scores[i0];
    float v1 = g_pos[i0+1] * sqrtf(fmaxf(m1, 0.0f) + 1e-12f) * scores[i0+1];
    contrib = v0 + v1;
    s_part[warp] = contrib;
  }
  __syncthreads();
  if (tid == 0){
    double a = 0.0;
    for (int w = 0; w < 8; w++) a += (double)s_part[w];
    atomicAdd(&g_acc[b*8+4], a);
  }
}

// ---------------- K4: finalize ----------------
__global__ void k_fin(float* __restrict__ out, int out_size){
  double bin = 0.0, wid = 0.0, adds = 0.0;
  for (int b = 0; b < BB; b++){
    double posSum = g_acc[b*8+0];
    double piv = fmax(posSum, 1.0);
    bin  += g_acc[b*8+1] / fmax(g_acc[b*8+2], 1.0);
    wid  += g_acc[b*8+3] / piv;
    adds += g_acc[b*8+4] / piv;
  }
  bin /= BB; wid /= BB; adds /= BB;
  double total = bin + wid + 3.0*adds;
  if (out_size > 0) out[0] = (float)total;
  if (out_size > 1) out[1] = (float)bin;
  if (out_size > 2) out[2] = (float)wid;
  if (out_size > 3) out[3] = (float)adds;
}

extern "C" void kernel_launch(void* const* d_in, const int* in_sizes, int n_in,
                              void* d_out, int out_size){
  const float* pred_grasps = (const float*)d_in[0];   // (4,2048,4,4)
  const float* pred_scores = (const float*)d_in[1];   // (4,2048,1)
  const float* pred_points = (const float*)d_in[2];   // (4,2048,3)
  const float* gwh         = (const float*)d_in[3];   // (4,10,2048)
  const float* pcp         = (const float*)d_in[4];   // (4,4096,3)
  const float* pcw         = (const float*)d_in[5];   // (4,4096)
  const float* pcr         = (const float*)d_in[6];   // (4,4096,3,3)
  const float* pct         = (const float*)d_in[7];   // (4,4096,3)
  const float* cp          = (const float*)d_in[8];   // (1,5,3)
  const float* cps         = (const float*)d_in[9];   // (1,5,3)

  k_prep<<<64, 256>>>(pcp);
  k_nn  <<<BB*NN/32, 256>>>(pred_points, pcw, pcr, pct, cp, cps);
  k_sel <<<BB*NN/8, 256>>>(pred_scores, gwh);
  k_adds<<<BB*NN/16, 256>>>(pred_grasps, pred_scores, cp);
  k_fin <<<1, 1>>>((float*)d_out, out_size);
}

// round 3
// speedup vs baseline: 2.4408x; 2.4408x over previous
// R3: factor k_adds' 15-dim dot into a 12-dim (R,t) dot; Q=4 register blocking;
// 80B-padded smem records (conflict-free); 256-wide j tiles. Rest unchanged.
#include <cuda_runtime.h>
#include <math.h>

#define BB 4
#define NN 2048
#define MM 4096
#define FARV 100000.0f

// ---------------- scratch (device globals; no allocation) ----------------
__device__ float4 g_pc4[BB*MM];          // contact points + norm
__device__ float  g_pos[BB*NN];          // success flag
__device__ float  g_pri[BB*NN];          // priority (r for negatives, +inf for positives)
__device__ float  g_wlab[BB*NN];         // gathered width label
__device__ float4 g_rec[BB*NN*4];        // per point: (R row0,t0)(R row1,t1)(R row2,t2)(gn,gsn,0,0)
__device__ double g_acc[BB*8];           // 0 posSum, 1 bceSum, 2 selSum, 3 wlSum, 4 addsSum

__constant__ float c_lo[10] = {0.0f, 0.00794435329f, 0.0158887021f, 0.0238330509f, 0.0317773996f,
                               0.0397217484f, 0.0476660972f, 0.0556104459f, 0.0635547947f, 0.0714991435f};
__constant__ float c_hi[10] = {0.00794435329f, 0.0158887021f, 0.0238330509f, 0.0317773996f, 0.0397217484f,
                               0.0476660972f, 0.0556104459f, 0.0635547947f, 0.0714991435f, 0.08f};
__constant__ float c_wt[10] = {0.16652107f, 0.21488856f, 0.37031708f, 0.55618503f, 0.75124664f,
                               0.93943357f, 1.07824539f, 1.19423112f, 1.55731375f, 2.34173634f};

// ---------------- threefry2x32 (JAX-exact, key(42), counts = iota(8192)) ----------------
__device__ __forceinline__ unsigned rotl32(unsigned x, unsigned d){ return (x<<d)|(x>>(32u-d)); }

__device__ __forceinline__ float threefry_uniform_8192(unsigned flat){
  unsigned c0, c1; bool second;
  if (flat < 4096u){ c0 = flat;        c1 = flat + 4096u; second = false; }
  else             { c0 = flat - 4096u; c1 = flat;        second = true;  }
  const unsigned ks0 = 0u, ks1 = 42u, ks2 = 0u ^ 42u ^ 0x1BD11BDAu;
  unsigned x0 = c0 + ks0, x1 = c1 + ks1;
#define TF_ROUND(r) { x0 += x1; x1 = rotl32(x1,(r)); x1 ^= x0; }
  TF_ROUND(13) TF_ROUND(15) TF_ROUND(26) TF_ROUND(6)
  x0 += ks1; x1 += ks2 + 1u;
  TF_ROUND(17) TF_ROUND(29) TF_ROUND(16) TF_ROUND(24)
  x0 += ks2; x1 += ks0 + 2u;
  TF_ROUND(13) TF_ROUND(15) TF_ROUND(26) TF_ROUND(6)
  x0 += ks0; x1 += ks1 + 3u;
  TF_ROUND(17) TF_ROUND(29) TF_ROUND(16) TF_ROUND(24)
  x0 += ks1; x1 += ks2 + 4u;
  TF_ROUND(13) TF_ROUND(15) TF_ROUND(26) TF_ROUND(6)
  x0 += ks2; x1 += ks0 + 5u;
#undef TF_ROUND
  unsigned bits = second ? x1 : x0;
  float f = __uint_as_float((bits >> 9) | 0x3F800000u) - 1.0f;
  return fmaxf(f, 0.0f);
}

// ---------------- K0: prep contact float4 + zero accumulators ----------------
__global__ void k_prep(const float* __restrict__ pcp){
  int i = blockIdx.x*blockDim.x + threadIdx.x;
  if (i < BB*8) g_acc[i] = 0.0;
  if (i < BB*MM){
    float x = pcp[i*3+0], y = pcp[i*3+1], z = pcp[i*3+2];
    g_pc4[i] = make_float4(x, y, z, x*x + y*y + z*z);
  }
}

// ---------------- K1: nearest neighbor + threefry + (R,t,gn,gsn) record ----------------
// warp handles 4 queries; block = 8 warps = 32 queries (batch-aligned)
__global__ __launch_bounds__(256) void k_nn(
    const float* __restrict__ pred_points,
    const float* __restrict__ pcw,
    const float* __restrict__ pcr,
    const float* __restrict__ pct,
    const float* __restrict__ cp,
    const float* __restrict__ cps)
{
  __shared__ float s_cp[15], s_cps[15];
  __shared__ float s_psum[8];
  int tid = threadIdx.x, lane = tid & 31, warp = tid >> 5;
  if (tid < 15){ s_cp[tid] = cp[tid]; s_cps[tid] = cps[tid]; }
  __syncthreads();

  int q0 = (blockIdx.x*8 + warp)*4;
  int b  = q0 / NN;

  float qx[4], qy[4], qz[4], qn[4];
#pragma unroll
  for (int k = 0; k < 4; k++){
    const float* p = pred_points + (size_t)(q0+k)*3;
    qx[k]=p[0]; qy[k]=p[1]; qz[k]=p[2];
    qn[k]=qx[k]*qx[k]+qy[k]*qy[k]+qz[k]*qz[k];
  }
  float best[4] = {3.4e38f,3.4e38f,3.4e38f,3.4e38f};
  int   bidx[4] = {0,0,0,0};
  const float4* pc = g_pc4 + (size_t)b*MM;
  for (int j = lane; j < MM; j += 32){
    float4 c = pc[j];
#pragma unroll
    for (int k = 0; k < 4; k++){
      float dot = qx[k]*c.x + qy[k]*c.y + qz[k]*c.z;
      float d = qn[k] + c.w - 2.0f*dot;
      d = fmaxf(d, 0.0f);
      if (d < best[k]){ best[k] = d; bidx[k] = j; }
    }
  }
#pragma unroll
  for (int k = 0; k < 4; k++){
#pragma unroll
    for (int off = 16; off; off >>= 1){
      float ov = __shfl_xor_sync(0xffffffffu, best[k], off);
      int   oi = __shfl_xor_sync(0xffffffffu, bidx[k], off);
      if (ov < best[k] || (ov == best[k] && oi < bidx[k])){ best[k]=ov; bidx[k]=oi; }
    }
  }

  float myPos = 0.0f;
  if (lane < 4){
    int k = lane;
    int q = q0 + k;
    int mi = bidx[k];
    float success = (best[k] < 2.5e-5f) ? 1.0f : 0.0f;  // RADIUS^2
    myPos = success;
    g_pos[q]  = success;
    g_wlab[q] = pcw[(size_t)b*MM + mi];
    float r = threefry_uniform_8192((unsigned)q);
    g_pri[q] = (success > 0.5f) ? __int_as_float(0x7f800000) : r;

    float Rm[9], Tv[3];
    if (success > 0.5f){
      const float* rp = pcr + ((size_t)b*MM + mi)*9;
#pragma unroll
      for (int u = 0; u < 9; u++) Rm[u] = rp[u];
      const float* tp = pct + ((size_t)b*MM + mi)*3;
      Tv[0]=tp[0]; Tv[1]=tp[1]; Tv[2]=tp[2];
    } else {
#pragma unroll
      for (int u = 0; u < 9; u++) Rm[u] = FARV;
      Tv[0]=FARV; Tv[1]=FARV; Tv[2]=FARV;
    }
    // gn = |R cp + t|^2 summed over control points (same arithmetic as before)
    float gn = 0.0f, gsn = 0.0f;
#pragma unroll
    for (int c = 0; c < 5; c++){
#pragma unroll
      for (int d = 0; d < 3; d++){
        float v  = Rm[d*3+0]*s_cp [c*3+0] + Rm[d*3+1]*s_cp [c*3+1] + Rm[d*3+2]*s_cp [c*3+2] + Tv[d];
        float vs = Rm[d*3+0]*s_cps[c*3+0] + Rm[d*3+1]*s_cps[c*3+1] + Rm[d*3+2]*s_cps[c*3+2] + Tv[d];
        gn  += v*v;
        gsn += vs*vs;
      }
    }
    float4* rec = g_rec + (size_t)q*4;
    rec[0] = make_float4(Rm[0], Rm[1], Rm[2], Tv[0]);
    rec[1] = make_float4(Rm[3], Rm[4], Rm[5], Tv[1]);
    rec[2] = make_float4(Rm[6], Rm[7], Rm[8], Tv[2]);
    rec[3] = make_float4(gn, gsn, 0.0f, 0.0f);
  }

  // block reduce posSum (all warps in block are in same batch)
  float ps = myPos;
#pragma unroll
  for (int off = 16; off; off >>= 1) ps += __shfl_xor_sync(0xffffffffu, ps, off);
  if (lane == 0) s_psum[warp] = ps;
  __syncthreads();
  if (tid == 0){
    double t = 0.0;
    for (int w = 0; w < 8; w++) t += (double)s_psum[w];
    atomicAdd(&g_acc[b*8+0], t);
  }
}

// ---------------- K2: rank-based negative selection + bce + width loss ----------------
// warp per element; block = 8 warps (batch-aligned)
__global__ __launch_bounds__(256) void k_sel(
    const float* __restrict__ scores,
    const float* __restrict__ gwh)
{
  __shared__ float sb[8], ss[8], sw[8];
  int tid = threadIdx.x, lane = tid & 31, warp = tid >> 5;
  int i = blockIdx.x*8 + warp;
  int b = i / NN, n = i % NN;

  float mypri = g_pri[i];
  const float* pri = g_pri + (size_t)b*NN;
  int cnt = 0;
  for (int j = lane; j < NN; j += 32){
    float pj = pri[j];
    if (pj < mypri || (pj == mypri && j < n)) cnt++;
  }
#pragma unroll
  for (int off = 16; off; off >>= 1) cnt += __shfl_xor_sync(0xffffffffu, cnt, off);

  float bcesel = 0.0f, selv = 0.0f, wlc = 0.0f;
  if (lane == 0){
    float pos = g_pos[i];
    float neg = 1.0f - pos;
    double nPos = g_acc[b*8+0];
    float kk = (nPos > 0.0) ? (float)nPos : 2.0f;
    float sel_neg = (neg > 0.5f && (float)cnt < kk) ? 1.0f : 0.0f;
    float sel = pos + sel_neg;
    float p = scores[i];
    p = fminf(fmaxf(p, 1e-7f), 1.0f - 1e-7f);
    float bce = -(pos*logf(p) + (1.0f - pos)*logf(1.0f - p));
    bcesel = bce*sel; selv = sel;

    float w = g_wlab[i];
    float acc = 0.0f;
#pragma unroll
    for (int kb = 0; kb < 10; kb++){
      float mh = (w >= c_lo[kb] && w < c_hi[kb]) ? 1.0f : 0.0f;
      float x = gwh[(size_t)b*10*NN + (size_t)kb*NN + n];
      float bw = fmaxf(x, 0.0f) - x*mh + log1pf(expf(-fabsf(x)));
      acc += c_wt[kb]*bw;
    }
    wlc = (acc * 0.1f) * pos;
  }
  if (lane == 0){ sb[warp]=bcesel; ss[warp]=selv; sw[warp]=wlc; }
  __syncthreads();
  if (tid == 0){
    double a=0, c=0, d=0;
    for (int w = 0; w < 8; w++){ a += (double)sb[w]; c += (double)ss[w]; d += (double)sw[w]; }
    atomicAdd(&g_acc[b*8+1], a);
    atomicAdd(&g_acc[b*8+2], c);
    atomicAdd(&g_acc[b*8+3], d);
  }
}

// ---------------- K3: ADD-S via 12-dim factored dot ----------------
// cross(P_i, G_j)  = <S_i , R_j> + <sumP_i, t_j>,  S_i[d][e] = sum_c P[i,c,d]*cp[c][e]
// cross(P_i, Gs_j) = <S'_i, R_j> + <sumP_i, t_j>,  S'_i with cps.
// Per-j smem record: 4 float4 padded to 5 (80 B stride, conflict-free LDS.128).
// warp handles 4 queries; block = 4 warps = 16 queries; j tiled 256/tile.
#define JT 256
__global__ __launch_bounds__(128) void k_adds(
    const float* __restrict__ grasps,
    const float* __restrict__ scores,
    const float* __restrict__ cp,
    const float* __restrict__ cps)
{
  __shared__ float4 sR[JT*5];
  __shared__ float  s_cp[15], s_cps[15];
  __shared__ float  s_part[4];

  int tid = threadIdx.x, lane = tid & 31, warp = tid >> 5;
  if (tid < 15){ s_cp[tid] = cp[tid]; s_cps[tid] = cps[tid]; }
  __syncthreads();

  int iBase = blockIdx.x*16;
  int b  = iBase / NN;
  int i0 = iBase + warp*4;

  // per-query features: A (for G) and As (for Gs), each 12 floats laid out
  // [d*4+e]: e=0..2 -> S[d][e], e=3 -> sumP[d]; plus pn.
  float A[4][12], As[4][12], pn[4];
#pragma unroll
  for (int q = 0; q < 4; q++){
    const float* gm = grasps + (size_t)(i0+q)*16;
    float P[15];
    float pq = 0.0f;
#pragma unroll
    for (int c = 0; c < 5; c++)
#pragma unroll
      for (int d = 0; d < 3; d++){
        float v = gm[d*4+0]*s_cp[c*3+0] + gm[d*4+1]*s_cp[c*3+1] + gm[d*4+2]*s_cp[c*3+2] + gm[d*4+3];
        P[c*3+d] = v; pq += v*v;
      }
    pn[q] = pq;
#pragma unroll
    for (int d = 0; d < 3; d++){
      float s0=0, s1=0, s2=0, sp=0;
      float t0=0, t1=0, t2=0;
#pragma unroll
      for (int c = 0; c < 5; c++){
        float pv = P[c*3+d];
        s0 += pv*s_cp [c*3+0]; s1 += pv*s_cp [c*3+1]; s2 += pv*s_cp [c*3+2];
        t0 += pv*s_cps[c*3+0]; t1 += pv*s_cps[c*3+1]; t2 += pv*s_cps[c*3+2];
        sp += pv;
      }
      A [q][d*4+0]=s0; A [q][d*4+1]=s1; A [q][d*4+2]=s2; A [q][d*4+3]=sp;
      As[q][d*4+0]=t0; As[q][d*4+1]=t1; As[q][d*4+2]=t2; As[q][d*4+3]=sp;
    }
  }

  float m[4] = {3.4e38f, 3.4e38f, 3.4e38f, 3.4e38f};
  for (int t = 0; t < NN/JT; t++){
    __syncthreads();
    int jb = t*JT;
    const float4* Rp = g_rec + ((size_t)b*NN + jb)*4;
    for (int u = tid; u < JT*4; u += 128) sR[(u>>2)*5 + (u&3)] = Rp[u];
    __syncthreads();
#pragma unroll
    for (int u = 0; u < JT/32; u++){
      int jj = lane + u*32;
      float4 r0 = sR[jj*5+0];
      float4 r1 = sR[jj*5+1];
      float4 r2 = sR[jj*5+2];
      float4 r3 = sR[jj*5+3];
#pragma unroll
      for (int q = 0; q < 4; q++){
        float cA = A[q][0]*r0.x + A[q][1]*r0.y + A[q][2]*r0.z + A[q][3]*r0.w
                 + A[q][4]*r1.x + A[q][5]*r1.y + A[q][6]*r1.z + A[q][7]*r1.w
                 + A[q][8]*r2.x + A[q][9]*r2.y + A[q][10]*r2.z + A[q][11]*r2.w;
        float cS = As[q][0]*r0.x + As[q][1]*r0.y + As[q][2]*r0.z + As[q][3]*r0.w
                 + As[q][4]*r1.x + As[q][5]*r1.y + As[q][6]*r1.z + As[q][7]*r1.w
                 + As[q][8]*r2.x + As[q][9]*r2.y + As[q][10]*r2.z + As[q][11]*r2.w;
        float dG  = pn[q] + r3.x - 2.0f*cA;
        float dGs = pn[q] + r3.y - 2.0f*cS;
        m[q] = fminf(m[q], fminf(dG, dGs));
      }
    }
  }
#pragma unroll
  for (int q = 0; q < 4; q++)
#pragma unroll
    for (int off = 16; off; off >>= 1)
      m[q] = fminf(m[q], __shfl_xor_sync(0xffffffffu, m[q], off));

  if (lane == 0){
    float contrib = 0.0f;
#pragma unroll
    for (int q = 0; q < 4; q++)
      contrib += g_pos[i0+q] * sqrtf(fmaxf(m[q], 0.0f) + 1e-12f) * scores[i0+q];
    s_part[warp] = contrib;
  }
  __syncthreads();
  if (tid == 0){
    double a = 0.0;
    for (int w = 0; w < 4; w++) a += (double)s_part[w];
    atomicAdd(&g_acc[b*8+4], a);
  }
}

// ---------------- K4: finalize ----------------
__global__ void k_fin(float* __restrict__ out, int out_size){
  double bin = 0.0, wid = 0.0, adds = 0.0;
  for (int b = 0; b < BB; b++){
    double posSum = g_acc[b*8+0];
    double piv = fmax(posSum, 1.0);
    bin  += g_acc[b*8+1] / fmax(g_acc[b*8+2], 1.0);
    wid  += g_acc[b*8+3] / piv;
    adds += g_acc[b*8+4] / piv;
  }
  bin /= BB; wid /= BB; adds /= BB;
  double total = bin + wid + 3.0*adds;
  if (out_size > 0) out[0] = (float)total;
  if (out_size > 1) out[1] = (float)bin;
  if (out_size > 2) out[2] = (float)wid;
  if (out_size > 3) out[3] = (float)adds;
}

extern "C" void kernel_launch(void* const* d_in, const int* in_sizes, int n_in,
                              void* d_out, int out_size){
  const float* pred_grasps = (const float*)d_in[0];   // (4,2048,4,4)
  const float* pred_scores = (const float*)d_in[1];   // (4,2048,1)
  const float* pred_points = (const float*)d_in[2];   // (4,2048,3)
  const float* gwh         = (const float*)d_in[3];   // (4,10,2048)
  const float* pcp         = (const float*)d_in[4];   // (4,4096,3)
  const float* pcw         = (const float*)d_in[5];   // (4,4096)
  const float* pcr         = (const float*)d_in[6];   // (4,4096,3,3)
  const float* pct         = (const float*)d_in[7];   // (4,4096,3)
  const float* cp          = (const float*)d_in[8];   // (1,5,3)
  const float* cps         = (const float*)d_in[9];   // (1,5,3)

  k_prep<<<64, 256>>>(pcp);
  k_nn  <<<BB*NN/32, 256>>>(pred_points, pcw, pcr, pct, cp, cps);
  k_sel <<<BB*NN/8, 256>>>(pred_scores, gwh);
  k_adds<<<BB*NN/16, 128>>>(pred_grasps, pred_scores, cp, cps);
  k_fin <<<1, 1>>>((float*)d_out, out_size);
}